// round 2
// baseline (speedup 1.0000x reference)
#include <cuda_runtime.h>
#include <math.h>

// ---------------------------------------------------------------------------
// TriplaneDecoder: fused triplane bilinear sampling + 10-layer MLP + heads
// B=4, N=100000, C=64, H=W=256, HID=256, NHID=10
//
// Stage 1 (prolog, per replay): transpose triplane [B,3,C,H,W]->[B,3,H,W,C]
//          and weights [o,k]->[k,o] into __device__ scratch.
// Stage 2 : one CTA per 64 points. Sample feats into smem (layout [p][k]),
//          run 10 GEMM layers fp32 with 8x8 register tiles, then heads.
// ---------------------------------------------------------------------------

#define BB   4
#define NN   100000
#define CC   64
#define HH   256
#define WW   256
#define HID  256
#define TP   64       // points per CTA
#define NT   256      // threads per CTA
#define KC   32       // k-chunk staged in smem

// scratch (device globals are the sanctioned scratch; no allocs allowed)
__device__ float g_trip[(size_t)BB * 3 * HH * WW * CC];   // 201 MB, [b*3+pl][h][w][c]
__device__ float g_w0t[192 * 256];                        // [k][o]
__device__ float g_wht[9 * 256 * 256];                    // [l][k][o]

// ---------------- triplane transpose: [plane][C][HW] -> [plane][HW][C] ------
__global__ void transpose_trip(const float* __restrict__ in) {
    __shared__ float s[64][33];
    const int plane = blockIdx.y;            // 0..11
    const int hw0   = blockIdx.x * 32;
    const float* ip = in + (size_t)plane * CC * HH * WW;
    float*       op = g_trip + (size_t)plane * HH * WW * CC;
    const int t = threadIdx.x;
    const int l32 = t & 31, grp = t >> 5;    // grp 0..7
#pragma unroll
    for (int i = 0; i < 8; i++) {
        int c = grp + i * 8;                 // 0..63
        s[c][l32] = ip[(size_t)c * (HH * WW) + hw0 + l32];
    }
    __syncthreads();
    const int c2 = t & 63, r0 = t >> 6;      // r0 0..3
#pragma unroll
    for (int j = 0; j < 8; j++) {
        int r = r0 + j * 4;                  // 0..31
        op[(size_t)(hw0 + r) * CC + c2] = s[c2][r];
    }
}

// ---------------- weight transpose ------------------------------------------
__global__ void transpose_w(const float* __restrict__ w_in,
                            const float* __restrict__ w_hid) {
    int i = blockIdx.x * blockDim.x + threadIdx.x;
    if (i < 192 * 256) {
        int k = i >> 8, o = i & 255;
        g_w0t[i] = w_in[o * 192 + k];
    }
    int j = i - 192 * 256;
    if (j >= 0 && j < 9 * 256 * 256) {
        int l = j >> 16, rem = j & 65535;
        int k = rem >> 8, o = rem & 255;
        g_wht[j] = w_hid[l * 65536 + o * 256 + k];
    }
}

// ---------------- fused decoder ---------------------------------------------
__global__ void __launch_bounds__(NT, 1)
decoder_kernel(const float* __restrict__ points,
               const float* __restrict__ b_in,
               const float* __restrict__ b_hid,
               const float* __restrict__ w_rgb, const float* __restrict__ b_rgb,
               const float* __restrict__ w_den, const float* __restrict__ b_den,
               const float* __restrict__ w_emb, const float* __restrict__ b_emb,
               float* __restrict__ out) {
    extern __shared__ float sm[];
    float* h_a  = sm;                        // [64][256]
    float* h_b  = h_a + TP * 256;            // [64][256]
    float* w_s  = h_b + TP * 256;            // [KC][256]
    float* wh_s = w_s + KC * 256;            // [7][256] head weights
    float* bh_s = wh_s + 7 * 256;            // [7]

    const int t    = threadIdx.x;
    const int lane = t & 31;
    const int wid  = t >> 5;                 // 0..7
    const int g0   = blockIdx.x * TP;

    // stage head weights/biases
    for (int i = t; i < 256 * 3; i += NT) wh_s[i]           = w_rgb[i];
    for (int i = t; i < 256;     i += NT) wh_s[3 * 256 + i] = w_den[i];
    for (int i = t; i < 256 * 3; i += NT) wh_s[4 * 256 + i] = w_emb[i];
    if (t < 3)            bh_s[t] = b_rgb[t];
    else if (t == 3)      bh_s[3] = b_den[0];
    else if (t < 7)       bh_s[t] = b_emb[t - 4];

    // ---- sampling: task = (point, plane), one warp per task -----------------
    for (int task = wid; task < TP * 3; task += 8) {
        const int p  = task / 3;
        const int pl = task - p * 3;
        const int g  = g0 + p;
        const int b  = g / NN;
        const float px = points[(size_t)g * 3 + 0];
        const float py = points[(size_t)g * 3 + 1];
        const float pz = points[(size_t)g * 3 + 2];
        float gx, gy;
        if (pl == 0)      { gx = px; gy = py; }
        else if (pl == 1) { gx = px; gy = pz; }
        else              { gx = py; gy = pz; }
        const float ix = (gx + 1.0f) * 0.5f * (float)(WW - 1);
        const float iy = (gy + 1.0f) * 0.5f * (float)(HH - 1);
        const float x0f = floorf(ix), y0f = floorf(iy);
        const float wx = ix - x0f, wy = iy - y0f;
        const int x0 = min(max((int)x0f,     0), WW - 1);
        const int x1 = min(max((int)x0f + 1, 0), WW - 1);
        const int y0 = min(max((int)y0f,     0), HH - 1);
        const int y1 = min(max((int)y0f + 1, 0), HH - 1);
        const float* base = g_trip + (size_t)(b * 3 + pl) * (HH * WW) * CC;
        const float2* c00 = (const float2*)(base + ((size_t)y0 * WW + x0) * CC);
        const float2* c01 = (const float2*)(base + ((size_t)y0 * WW + x1) * CC);
        const float2* c10 = (const float2*)(base + ((size_t)y1 * WW + x0) * CC);
        const float2* c11 = (const float2*)(base + ((size_t)y1 * WW + x1) * CC);
        const float w00 = (1.0f - wx) * (1.0f - wy);
        const float w01 = wx * (1.0f - wy);
        const float w10 = (1.0f - wx) * wy;
        const float w11 = wx * wy;
        const float2 v00 = c00[lane], v01 = c01[lane];
        const float2 v10 = c10[lane], v11 = c11[lane];
        float2 r;
        r.x = v00.x * w00 + v01.x * w01 + v10.x * w10 + v11.x * w11;
        r.y = v00.y * w00 + v01.y * w01 + v10.y * w10 + v11.y * w11;
        ((float2*)(h_a + p * 256 + pl * 64))[lane] = r;   // feats: h_a[p][0..191]
    }

    // ---- 10 GEMM layers ------------------------------------------------------
    // thread (pi=wid, oi=lane): 8 points x 8 outputs register tile.
    // Output rows: {oi*4 .. oi*4+3} and {128+oi*4 .. 128+oi*4+3}  (conflict-free
    // LDS.128 weight reads: each warp instruction covers 512 contiguous bytes).
    const int oi = lane, pi = wid;
    const float* in = h_a;
    float* outp = h_b;

    for (int L = 0; L < 10; L++) {
        const int kdim = (L == 0) ? 192 : 256;
        const float* wt   = (L == 0) ? g_w0t : (g_wht + (size_t)(L - 1) * 65536);
        const float* bptr = (L == 0) ? b_in : (b_hid + (L - 1) * 256);

        float acc[8][8];
#pragma unroll
        for (int r = 0; r < 4; r++) {
            const float bv0 = __ldg(bptr + oi * 4 + r);
            const float bv1 = __ldg(bptr + 128 + oi * 4 + r);
#pragma unroll
            for (int c = 0; c < 8; c++) { acc[r][c] = bv0; acc[4 + r][c] = bv1; }
        }

        const int nchunks = kdim / KC;
        for (int ch = 0; ch < nchunks; ch++) {
            __syncthreads();                              // w_s free, prev writes visible
            const float4* wg4 = (const float4*)(wt + (size_t)ch * KC * 256);
            float4* ws4 = (float4*)w_s;
#pragma unroll
            for (int i = 0; i < (KC * 256 / 4) / NT; i++) // 8 iters
                ws4[t + i * NT] = wg4[t + i * NT];
            __syncthreads();

            const float* inp = in + pi * 8 * 256 + ch * KC;
#pragma unroll 8
            for (int kk = 0; kk < KC; kk++) {
                const float4 w0 = *(const float4*)&w_s[kk * 256 + oi * 4];
                const float4 w1 = *(const float4*)&w_s[kk * 256 + 128 + oi * 4];
                float hv[8];
#pragma unroll
                for (int c = 0; c < 8; c++) hv[c] = inp[c * 256 + kk];
#pragma unroll
                for (int c = 0; c < 8; c++) {
                    acc[0][c] += hv[c] * w0.x;
                    acc[1][c] += hv[c] * w0.y;
                    acc[2][c] += hv[c] * w0.z;
                    acc[3][c] += hv[c] * w0.w;
                    acc[4][c] += hv[c] * w1.x;
                    acc[5][c] += hv[c] * w1.y;
                    acc[6][c] += hv[c] * w1.z;
                    acc[7][c] += hv[c] * w1.w;
                }
            }
        }

        // relu + store (outp != in, outp != w_s -> safe without extra sync)
#pragma unroll
        for (int c = 0; c < 8; c++) {
            float4 v0, v1;
            v0.x = fmaxf(acc[0][c], 0.0f); v0.y = fmaxf(acc[1][c], 0.0f);
            v0.z = fmaxf(acc[2][c], 0.0f); v0.w = fmaxf(acc[3][c], 0.0f);
            v1.x = fmaxf(acc[4][c], 0.0f); v1.y = fmaxf(acc[5][c], 0.0f);
            v1.z = fmaxf(acc[6][c], 0.0f); v1.w = fmaxf(acc[7][c], 0.0f);
            *(float4*)&outp[(pi * 8 + c) * 256 + oi * 4]       = v0;
            *(float4*)&outp[(pi * 8 + c) * 256 + 128 + oi * 4] = v1;
        }
        // swap ping-pong
        const float* tmp = in; in = outp; outp = (float*)tmp;
    }
    __syncthreads();

    // ---- heads: rgb(3, sigmoid), density(1), embedding(3) -------------------
    // after 10 layers (even count), `in` points at the final h buffer (h_a)
    const float* hf = in;
    for (int task = wid; task < TP * 7; task += 8) {
        const int p = task & 63;
        const int j = task >> 6;                 // 0..6
        const float4* hp = (const float4*)(hf + p * 256);
        const float4* wp = (const float4*)(wh_s + j * 256);
        float s = 0.0f;
#pragma unroll
        for (int ii = 0; ii < 2; ii++) {
            const float4 hv = hp[lane + ii * 32];
            const float4 wv = wp[lane + ii * 32];
            s += hv.x * wv.x + hv.y * wv.y + hv.z * wv.z + hv.w * wv.w;
        }
#pragma unroll
        for (int off = 16; off; off >>= 1) s += __shfl_xor_sync(0xFFFFFFFFu, s, off);
        if (lane == 0) {
            s += bh_s[j];
            const int g = g0 + p;
            if (j < 3)
                out[(size_t)g * 3 + j] = 1.0f / (1.0f + expf(-s));        // rgb
            else if (j == 3)
                out[(size_t)BB * NN * 3 + g] = s;                          // density
            else
                out[(size_t)BB * NN * 4 + (size_t)g * 3 + (j - 4)] = s;    // embedding
        }
    }
}

// ---------------------------------------------------------------------------
extern "C" void kernel_launch(void* const* d_in, const int* in_sizes, int n_in,
                              void* d_out, int out_size) {
    const float* triplane = (const float*)d_in[0];
    const float* points   = (const float*)d_in[1];
    const float* w_in     = (const float*)d_in[2];
    const float* b_in     = (const float*)d_in[3];
    const float* w_hid    = (const float*)d_in[4];
    const float* b_hid    = (const float*)d_in[5];
    const float* w_rgb    = (const float*)d_in[6];
    const float* b_rgb    = (const float*)d_in[7];
    const float* w_den    = (const float*)d_in[8];
    const float* b_den    = (const float*)d_in[9];
    const float* w_emb    = (const float*)d_in[10];
    const float* b_emb    = (const float*)d_in[11];
    float* out = (float*)d_out;

    // prolog: re-layout triplane (channel-last) and weights ([k][o])
    transpose_trip<<<dim3((HH * WW) / 32, BB * 3), 256>>>(triplane);
    transpose_w<<<(192 * 256 + 9 * 256 * 256 + 255) / 256, 256>>>(w_in, w_hid);

    const size_t smem = (size_t)(TP * 256 * 2 + KC * 256 + 7 * 256 + 8) * sizeof(float);
    cudaFuncSetAttribute(decoder_kernel,
                         cudaFuncAttributeMaxDynamicSharedMemorySize, (int)smem);
    decoder_kernel<<<(BB * NN) / TP, NT, smem>>>(
        points, b_in, b_hid, w_rgb, b_rgb, w_den, b_den, w_emb, b_emb, out);
}

// round 4
// speedup vs baseline: 1.8791x; 1.8791x over previous
#include <cuda_runtime.h>
#include <cuda_bf16.h>
#include <math.h>
#include <stdint.h>

// ---------------------------------------------------------------------------
// TriplaneDecoder via warp-level bf16 HMMA (mma.sync) — compute_100-safe.
// 3-term bf16 hi/lo split GEMMs: D = AhBh + AlBh + AhBl  (fp32 accum).
// CTA = 128 points; 8 warps in 2(M)x4(N); warp tile 64x64; K chunked by 32.
// Activations: smem bf16 hi/lo planes, XOR-swizzled for ldmatrix.
// Weights: prolog pre-splits hi/lo + pre-swizzles in gmem -> linear cp.async.
// ---------------------------------------------------------------------------

#define BB 4
#define NN 100000
#define CC 64
#define HH 256
#define WW 256
#define PTS 128
#define NTH 256
#define NCHUNK_TOT 78          // L0: 6 chunks (K=192), L1..9: 8 chunks each

// smem byte offsets
#define SO_AHI   0             // A hi plane: 128 rows x 512B
#define SO_ALO   65536         // A lo plane
#define SO_WBUF  131072        // 2 x 32KB weight chunk buffers (hi 16KB | lo 16KB)
#define SO_SB    196608        // biases 10*256 f32
#define SO_WHT   206848        // head weights [256][8] f32
#define SO_BHD   215040        // head biases [8]
#define SMEM_TOT 215072

// device scratch
__device__ float g_trip[(size_t)BB * 3 * HH * WW * CC];
__device__ uint4 g_wq[2555904 / 16];   // pre-swizzled bf16 hi/lo weight chunks

// ---- PTX helpers -----------------------------------------------------------
__device__ __forceinline__ uint32_t smem_u32(const void* p) {
    uint32_t a;
    asm("{ .reg .u64 t; cvta.to.shared.u64 t, %1; cvt.u32.u64 %0, t; }" : "=r"(a) : "l"(p));
    return a;
}
__device__ __forceinline__ void ldsm4(uint32_t* r, uint32_t a) {
    asm volatile("ldmatrix.sync.aligned.m8n8.x4.shared.b16 {%0,%1,%2,%3}, [%4];"
                 : "=r"(r[0]), "=r"(r[1]), "=r"(r[2]), "=r"(r[3]) : "r"(a));
}
__device__ __forceinline__ void ldsm4t(uint32_t* r, uint32_t a) {
    asm volatile("ldmatrix.sync.aligned.m8n8.x4.trans.shared.b16 {%0,%1,%2,%3}, [%4];"
                 : "=r"(r[0]), "=r"(r[1]), "=r"(r[2]), "=r"(r[3]) : "r"(a));
}
__device__ __forceinline__ void mma16816(float* c, const uint32_t* a, const uint32_t* b) {
    asm volatile("mma.sync.aligned.m16n8k16.row.col.f32.bf16.bf16.f32 "
                 "{%0,%1,%2,%3}, {%4,%5,%6,%7}, {%8,%9}, {%0,%1,%2,%3};"
                 : "+f"(c[0]), "+f"(c[1]), "+f"(c[2]), "+f"(c[3])
                 : "r"(a[0]), "r"(a[1]), "r"(a[2]), "r"(a[3]), "r"(b[0]), "r"(b[1]));
}
#define CP_ASYNC16(dst, src) \
    asm volatile("cp.async.cg.shared.global [%0], [%1], 16;" :: "r"(dst), "l"(src))
#define CP_COMMIT() asm volatile("cp.async.commit_group;")
#define CP_WAIT0()  asm volatile("cp.async.wait_group 0;")
// pack two fp32 -> bf16x2 (low half = a, high half = b)
#define PACKBF(res, a, b) \
    asm("cvt.rn.satfinite.bf16x2.f32 %0, %1, %2;" : "=r"(res) : "f"(b), "f"(a))

// ---------------- prolog 1: triplane [pl][C][HW] -> [pl][HW][C] -------------
__global__ void transpose_trip(const float* __restrict__ in) {
    __shared__ float s[64][33];
    const int plane = blockIdx.y;
    const int hw0 = blockIdx.x * 32;
    const float* ip = in + (size_t)plane * CC * HH * WW;
    float* op = g_trip + (size_t)plane * HH * WW * CC;
    const int t = threadIdx.x, l32 = t & 31, grp = t >> 5;
#pragma unroll
    for (int i = 0; i < 8; i++) {
        int c = grp + i * 8;
        s[c][l32] = ip[(size_t)c * (HH * WW) + hw0 + l32];
    }
    __syncthreads();
    const int c2 = t & 63, r0 = t >> 6;
#pragma unroll
    for (int j = 0; j < 8; j++) {
        int r = r0 + j * 4;
        op[(size_t)(hw0 + r) * CC + c2] = s[c2][r];
    }
}

// ---------------- prolog 2: weights -> bf16 hi/lo, chunked + swizzled --------
// chunk (32 k-rows): hi plane [32][256] bf16 (16KB) then lo plane (16KB).
// row = k&31 (512B), 16B-unit u at n>>3 stored at (u ^ (k&7)).
__global__ void prep_weights(const float* __restrict__ w_in,
                             const float* __restrict__ w_hid) {
    const int i = blockIdx.x * blockDim.x + threadIdx.x;
    uint8_t* gw = (uint8_t*)g_wq;
    float w;
    int k, n;
    size_t base;
    if (i < 49152) {                    // layer 0: w_in [256 n][192 k]
        n = i / 192; k = i - n * 192;
        w = w_in[i];
        base = (size_t)(k >> 5) * 32768;
    } else {
        const int j = i - 49152;
        if (j >= 9 * 65536) return;
        const int L = j >> 16, r = j & 65535;
        n = r >> 8; k = r & 255;
        w = w_hid[j];
        base = 196608u + (size_t)L * 262144u + (size_t)(k >> 5) * 32768u;
    }
    const size_t dst = base + (size_t)(k & 31) * 512
                     + (size_t)((((n >> 3) ^ (k & 7))) << 4) + (n & 7) * 2;
    __nv_bfloat16 hi = __float2bfloat16(w);
    float hf = __bfloat162float(hi);
    __nv_bfloat16 lo = __float2bfloat16(w - hf);
    *(__nv_bfloat16*)(gw + dst) = hi;
    *(__nv_bfloat16*)(gw + dst + 16384) = lo;
}

// ---------------- main fused decoder ----------------------------------------
__global__ void __launch_bounds__(NTH, 1)
decoder(const float* __restrict__ points,
        const float* __restrict__ b_in, const float* __restrict__ b_hid,
        const float* __restrict__ w_rgb, const float* __restrict__ b_rgb,
        const float* __restrict__ w_den, const float* __restrict__ b_den,
        const float* __restrict__ w_emb, const float* __restrict__ b_emb,
        float* __restrict__ out) {
    extern __shared__ char sm[];
    const uint32_t smb = smem_u32(sm);
    const int t = threadIdx.x, lane = t & 31, wid = t >> 5;
    const int wm = wid >> 2, wn = wid & 3;        // warp grid 2(M) x 4(N)
    const int g0 = blockIdx.x * PTS;
    const uint8_t* gw = (const uint8_t*)g_wq;

    // kick off weight chunk 0 load (overlaps sampling)
    {
        const uint32_t dst = smb + SO_WBUF;
#pragma unroll
        for (int i = 0; i < 8; i++) {
            const int off = (t + i * NTH) * 16;
            CP_ASYNC16(dst + off, gw + off);
        }
        CP_COMMIT();
    }

    // stage biases + head weights
    float* sb  = (float*)(sm + SO_SB);
    float* wht = (float*)(sm + SO_WHT);
    float* bhd = (float*)(sm + SO_BHD);
    for (int i = t; i < 2560; i += NTH) sb[i] = (i < 256) ? b_in[i] : b_hid[i - 256];
    for (int i = t; i < 256; i += NTH) {
        wht[i * 8 + 0] = w_rgb[i];        wht[i * 8 + 1] = w_rgb[256 + i];
        wht[i * 8 + 2] = w_rgb[512 + i];  wht[i * 8 + 3] = w_den[i];
        wht[i * 8 + 4] = w_emb[i];        wht[i * 8 + 5] = w_emb[256 + i];
        wht[i * 8 + 6] = w_emb[512 + i];  wht[i * 8 + 7] = 0.0f;
    }
    if (t < 3) bhd[t] = b_rgb[t];
    else if (t == 3) bhd[3] = b_den[0];
    else if (t < 7) bhd[t] = b_emb[t - 4];
    else if (t == 7) bhd[7] = 0.0f;

    // ---- sampling: one warp per (point, plane); write bf16 hi/lo into A -----
    for (int task = wid; task < PTS * 3; task += 8) {
        const int p = task / 3, pl = task - p * 3;
        const int g = g0 + p, b = g / NN;
        const float px = points[(size_t)g * 3 + 0];
        const float py = points[(size_t)g * 3 + 1];
        const float pz = points[(size_t)g * 3 + 2];
        float gx, gy;
        if (pl == 0)      { gx = px; gy = py; }
        else if (pl == 1) { gx = px; gy = pz; }
        else              { gx = py; gy = pz; }
        const float ix = (gx + 1.0f) * 0.5f * (float)(WW - 1);
        const float iy = (gy + 1.0f) * 0.5f * (float)(HH - 1);
        const float x0f = floorf(ix), y0f = floorf(iy);
        const float wx = ix - x0f, wy = iy - y0f;
        const int x0 = min(max((int)x0f, 0), WW - 1);
        const int x1 = min(max((int)x0f + 1, 0), WW - 1);
        const int y0 = min(max((int)y0f, 0), HH - 1);
        const int y1 = min(max((int)y0f + 1, 0), HH - 1);
        const float* base = g_trip + (size_t)(b * 3 + pl) * (HH * WW) * CC;
        const float2* c00 = (const float2*)(base + ((size_t)y0 * WW + x0) * CC);
        const float2* c01 = (const float2*)(base + ((size_t)y0 * WW + x1) * CC);
        const float2* c10 = (const float2*)(base + ((size_t)y1 * WW + x0) * CC);
        const float2* c11 = (const float2*)(base + ((size_t)y1 * WW + x1) * CC);
        const float w00 = (1.0f - wx) * (1.0f - wy), w01 = wx * (1.0f - wy);
        const float w10 = (1.0f - wx) * wy,          w11 = wx * wy;
        const float2 v00 = c00[lane], v01 = c01[lane];
        const float2 v10 = c10[lane], v11 = c11[lane];
        float rx = v00.x * w00 + v01.x * w01 + v10.x * w10 + v11.x * w11;
        float ry = v00.y * w00 + v01.y * w01 + v10.y * w10 + v11.y * w11;
        uint32_t hw; PACKBF(hw, rx, ry);
        float h0 = __uint_as_float(hw << 16);
        float h1 = __uint_as_float(hw & 0xFFFF0000u);
        uint32_t lw; PACKBF(lw, rx - h0, ry - h1);
        // word index wc = pl*32 + lane  (k = 2*wc), row p, swizzled
        const int wc = pl * 32 + lane;
        const uint32_t ad = smb + p * 512 + ((((wc >> 2) ^ (p & 7))) << 4) + (wc & 3) * 4;
        *(uint32_t*)(sm + (ad - smb)) = hw;                 // A hi
        *(uint32_t*)(sm + (ad - smb) + 65536) = lw;         // A lo
    }
    __syncthreads();

    // ---- 10 layers ----------------------------------------------------------
    int gc = 0;
    const int rowA = wm * 64 + (lane & 15);       // + mi*16
    const uint32_t swA = (uint32_t)(lane & 7);
    float hf_keep[0 + 1];                          // dummy to quiet compilers
    (void)hf_keep;

    for (int L = 0; L < 10; L++) {
        const int nch = (L == 0) ? 6 : 8;
        float acc[4][8][4];
        // bias init (bias of this layer baked into accumulators)
#pragma unroll
        for (int ni = 0; ni < 8; ni++) {
            const int col0 = wn * 64 + ni * 8 + 2 * (lane & 3);
            const float bv0 = sb[L * 256 + col0];
            const float bv1 = sb[L * 256 + col0 + 1];
#pragma unroll
            for (int mi = 0; mi < 4; mi++) {
                acc[mi][ni][0] = bv0; acc[mi][ni][1] = bv1;
                acc[mi][ni][2] = bv0; acc[mi][ni][3] = bv1;
            }
        }

        for (int c = 0; c < nch; c++) {
            CP_WAIT0();
            __syncthreads();
            if (gc + 1 < NCHUNK_TOT) {           // prefetch next chunk
                const uint32_t dst = smb + SO_WBUF + ((gc + 1) & 1) * 32768;
                const uint8_t* src = gw + (size_t)(gc + 1) * 32768;
#pragma unroll
                for (int i = 0; i < 8; i++) {
                    const int off = (t + i * NTH) * 16;
                    CP_ASYNC16(dst + off, src + off);
                }
                CP_COMMIT();
            }
            const uint32_t wb = smb + SO_WBUF + (gc & 1) * 32768;
#pragma unroll
            for (int s = 0; s < 2; s++) {
                const int ku = c * 4 + s * 2;     // A 16B-unit base for this k16
                uint32_t ah[4][4], al[4][4];
#pragma unroll
                for (int mi = 0; mi < 4; mi++) {
                    const uint32_t aA = smb + (rowA + mi * 16) * 512
                                      + ((((uint32_t)(ku + (lane >> 4))) ^ swA) << 4);
                    ldsm4(ah[mi], aA);
                    ldsm4(al[mi], aA + 65536);
                }
                const int rowB = s * 16 + (lane & 15);
#pragma unroll
                for (int nt = 0; nt < 4; nt++) {
                    uint32_t bh[4], bl[4];
                    const uint32_t ub = (uint32_t)(wn * 8 + nt * 2 + (lane >> 4));
                    const uint32_t aB = wb + rowB * 512 + ((ub ^ swA) << 4);
                    ldsm4t(bh, aB);
                    ldsm4t(bl, aB + 16384);
#pragma unroll
                    for (int mi = 0; mi < 4; mi++) {
                        mma16816(acc[mi][2 * nt],     ah[mi], bh);
                        mma16816(acc[mi][2 * nt + 1], ah[mi], bh + 2);
                        mma16816(acc[mi][2 * nt],     al[mi], bh);
                        mma16816(acc[mi][2 * nt + 1], al[mi], bh + 2);
                        mma16816(acc[mi][2 * nt],     ah[mi], bl);
                        mma16816(acc[mi][2 * nt + 1], ah[mi], bl + 2);
                    }
                }
            }
            gc++;
        }
        __syncthreads();   // all warps done reading A for this layer

        if (L < 9) {
            // epilogue: relu + bf16 hi/lo re-split -> A planes (swizzled)
#pragma unroll
            for (int mi = 0; mi < 4; mi++) {
#pragma unroll
                for (int ni = 0; ni < 8; ni++) {
                    float v0 = fmaxf(acc[mi][ni][0], 0.0f);
                    float v1 = fmaxf(acc[mi][ni][1], 0.0f);
                    float v2 = fmaxf(acc[mi][ni][2], 0.0f);
                    float v3 = fmaxf(acc[mi][ni][3], 0.0f);
                    const int r1 = wm * 64 + mi * 16 + (lane >> 2);
                    const uint32_t u = (uint32_t)((wn * 8 + ni) ^ ((lane >> 2) & 7));
                    const uint32_t a1 = r1 * 512 + (u << 4) + (lane & 3) * 4;
                    uint32_t hw, lw;
                    PACKBF(hw, v0, v1);
                    {
                        float h0 = __uint_as_float(hw << 16);
                        float h1 = __uint_as_float(hw & 0xFFFF0000u);
                        PACKBF(lw, v0 - h0, v1 - h1);
                    }
                    *(uint32_t*)(sm + a1) = hw;
                    *(uint32_t*)(sm + a1 + 65536) = lw;
                    PACKBF(hw, v2, v3);
                    {
                        float h0 = __uint_as_float(hw << 16);
                        float h1 = __uint_as_float(hw & 0xFFFF0000u);
                        PACKBF(lw, v2 - h0, v3 - h1);
                    }
                    *(uint32_t*)(sm + a1 + 4096) = hw;            // row +8
                    *(uint32_t*)(sm + a1 + 4096 + 65536) = lw;
                }
            }
        } else {
            // final layer: store fp32 h into A region (plain layout [p][256])
#pragma unroll
            for (int mi = 0; mi < 4; mi++) {
#pragma unroll
                for (int ni = 0; ni < 8; ni++) {
                    const int r1 = wm * 64 + mi * 16 + (lane >> 2);
                    const int col0 = wn * 64 + ni * 8 + 2 * (lane & 3);
                    float* d1 = (float*)(sm + r1 * 1024 + col0 * 4);
                    float* d2 = (float*)(sm + (r1 + 8) * 1024 + col0 * 4);
                    d1[0] = fmaxf(acc[mi][ni][0], 0.0f);
                    d1[1] = fmaxf(acc[mi][ni][1], 0.0f);
                    d2[0] = fmaxf(acc[mi][ni][2], 0.0f);
                    d2[1] = fmaxf(acc[mi][ni][3], 0.0f);
                }
            }
        }
        __syncthreads();
    }

    // ---- heads: rgb(3, sigmoid), density(1), embedding(3) -------------------
    const float* hf = (const float*)sm;           // [128][256] f32
    for (int task = wid; task < PTS * 7; task += 8) {
        const int p = task & 127;
        const int j = task >> 7;                  // 0..6
        const float4* hp = (const float4*)(hf + p * 256);
        const float4* wp = (const float4*)0;
        float s = 0.0f;
#pragma unroll
        for (int ii = 0; ii < 2; ii++) {
            const float4 hv = hp[lane + ii * 32];
            const int c0 = (lane + ii * 32) * 4;
            s += hv.x * wht[(c0 + 0) * 8 + j] + hv.y * wht[(c0 + 1) * 8 + j]
               + hv.z * wht[(c0 + 2) * 8 + j] + hv.w * wht[(c0 + 3) * 8 + j];
        }
        (void)wp;
#pragma unroll
        for (int off = 16; off; off >>= 1) s += __shfl_xor_sync(0xFFFFFFFFu, s, off);
        if (lane == 0) {
            s += bhd[j];
            const int g = g0 + p;
            if (j < 3)
                out[(size_t)g * 3 + j] = 1.0f / (1.0f + expf(-s));
            else if (j == 3)
                out[(size_t)BB * NN * 3 + g] = s;
            else
                out[(size_t)BB * NN * 4 + (size_t)g * 3 + (j - 4)] = s;
        }
    }
}

// ---------------------------------------------------------------------------
extern "C" void kernel_launch(void* const* d_in, const int* in_sizes, int n_in,
                              void* d_out, int out_size) {
    const float* triplane = (const float*)d_in[0];
    const float* points   = (const float*)d_in[1];
    const float* w_in     = (const float*)d_in[2];
    const float* b_in     = (const float*)d_in[3];
    const float* w_hid    = (const float*)d_in[4];
    const float* b_hid    = (const float*)d_in[5];
    const float* w_rgb    = (const float*)d_in[6];
    const float* b_rgb    = (const float*)d_in[7];
    const float* w_den    = (const float*)d_in[8];
    const float* b_den    = (const float*)d_in[9];
    const float* w_emb    = (const float*)d_in[10];
    const float* b_emb    = (const float*)d_in[11];
    float* out = (float*)d_out;

    transpose_trip<<<dim3((HH * WW) / 32, BB * 3), 256>>>(triplane);
    prep_weights<<<(49152 + 9 * 65536 + 255) / 256, 256>>>(w_in, w_hid);

    cudaFuncSetAttribute(decoder, cudaFuncAttributeMaxDynamicSharedMemorySize, SMEM_TOT);
    decoder<<<(BB * NN) / PTS, NTH, SMEM_TOT>>>(
        points, b_in, b_hid, w_rgb, b_rgb, w_den, b_den, w_emb, b_emb, out);
}

// round 5
// speedup vs baseline: 1.9418x; 1.0333x over previous
#include <cuda_runtime.h>
#include <cuda_bf16.h>
#include <math.h>
#include <stdint.h>

// ---------------------------------------------------------------------------
// TriplaneDecoder via warp-level bf16 HMMA (mma.sync) — compute_100-safe.
// 3-term bf16 hi/lo split GEMMs: D = AhBh + AlBh + AhBl  (fp32 accum).
// CTA = 128 points; 16 warps in 4(M)x4(N); warp tile 32x64; K chunked by 32.
// Activations: smem bf16 hi/lo planes, XOR-swizzled for ldmatrix.
// Weights: prolog pre-splits hi/lo + pre-swizzles in gmem -> linear cp.async.
// ---------------------------------------------------------------------------

#define BB 4
#define NN 100000
#define CC 64
#define HH 256
#define WW 256
#define PTS 128
#define NTH 512
#define NCHUNK_TOT 78          // L0: 6 chunks (K=192), L1..9: 8 chunks each

// smem byte offsets
#define SO_AHI   0             // A hi plane: 128 rows x 512B
#define SO_ALO   65536         // A lo plane
#define SO_WBUF  131072        // 2 x 32KB weight chunk buffers (hi 16KB | lo 16KB)
#define SO_SB    196608        // biases 10*256 f32
#define SO_WHT   206848        // head weights [256][8] f32
#define SO_BHD   215040        // head biases [8]
#define SMEM_TOT 215072

// device scratch
__device__ float g_trip[(size_t)BB * 3 * HH * WW * CC];
__device__ uint4 g_wq[2555904 / 16];   // pre-swizzled bf16 hi/lo weight chunks

// ---- PTX helpers -----------------------------------------------------------
__device__ __forceinline__ uint32_t smem_u32(const void* p) {
    uint32_t a;
    asm("{ .reg .u64 t; cvta.to.shared.u64 t, %1; cvt.u32.u64 %0, t; }" : "=r"(a) : "l"(p));
    return a;
}
__device__ __forceinline__ void ldsm4(uint32_t* r, uint32_t a) {
    asm volatile("ldmatrix.sync.aligned.m8n8.x4.shared.b16 {%0,%1,%2,%3}, [%4];"
                 : "=r"(r[0]), "=r"(r[1]), "=r"(r[2]), "=r"(r[3]) : "r"(a));
}
__device__ __forceinline__ void ldsm4t(uint32_t* r, uint32_t a) {
    asm volatile("ldmatrix.sync.aligned.m8n8.x4.trans.shared.b16 {%0,%1,%2,%3}, [%4];"
                 : "=r"(r[0]), "=r"(r[1]), "=r"(r[2]), "=r"(r[3]) : "r"(a));
}
__device__ __forceinline__ void mma16816(float* c, const uint32_t* a, const uint32_t* b) {
    asm volatile("mma.sync.aligned.m16n8k16.row.col.f32.bf16.bf16.f32 "
                 "{%0,%1,%2,%3}, {%4,%5,%6,%7}, {%8,%9}, {%0,%1,%2,%3};"
                 : "+f"(c[0]), "+f"(c[1]), "+f"(c[2]), "+f"(c[3])
                 : "r"(a[0]), "r"(a[1]), "r"(a[2]), "r"(a[3]), "r"(b[0]), "r"(b[1]));
}
#define CP_ASYNC16(dst, src) \
    asm volatile("cp.async.cg.shared.global [%0], [%1], 16;" :: "r"(dst), "l"(src))
#define CP_COMMIT() asm volatile("cp.async.commit_group;")
#define CP_WAIT0()  asm volatile("cp.async.wait_group 0;")
// pack two fp32 -> bf16x2 (low half = a, high half = b)
#define PACKBF(res, a, b) \
    asm("cvt.rn.satfinite.bf16x2.f32 %0, %1, %2;" : "=r"(res) : "f"(b), "f"(a))

// ---------------- prolog 1: triplane [pl][C][HW] -> [pl][HW][C] -------------
__global__ void transpose_trip(const float* __restrict__ in) {
    __shared__ float s[64][33];
    const int plane = blockIdx.y;
    const int hw0 = blockIdx.x * 32;
    const float* ip = in + (size_t)plane * CC * HH * WW;
    float* op = g_trip + (size_t)plane * HH * WW * CC;
    const int t = threadIdx.x, l32 = t & 31, grp = t >> 5;
#pragma unroll
    for (int i = 0; i < 8; i++) {
        int c = grp + i * 8;
        s[c][l32] = ip[(size_t)c * (HH * WW) + hw0 + l32];
    }
    __syncthreads();
    const int c2 = t & 63, r0 = t >> 6;
#pragma unroll
    for (int j = 0; j < 8; j++) {
        int r = r0 + j * 4;
        op[(size_t)(hw0 + r) * CC + c2] = s[c2][r];
    }
}

// ---------------- prolog 2: weights -> bf16 hi/lo, chunked + swizzled --------
// chunk (32 k-rows): hi plane [32][256] bf16 (16KB) then lo plane (16KB).
// row = k&31 (512B), 16B-unit u at n>>3 stored at (u ^ (k&7)).
__global__ void prep_weights(const float* __restrict__ w_in,
                             const float* __restrict__ w_hid) {
    const int i = blockIdx.x * blockDim.x + threadIdx.x;
    uint8_t* gw = (uint8_t*)g_wq;
    float w;
    int k, n;
    size_t base;
    if (i < 49152) {                    // layer 0: w_in [256 n][192 k]
        n = i / 192; k = i - n * 192;
        w = w_in[i];
        base = (size_t)(k >> 5) * 32768;
    } else {
        const int j = i - 49152;
        if (j >= 9 * 65536) return;
        const int L = j >> 16, r = j & 65535;
        n = r >> 8; k = r & 255;
        w = w_hid[j];
        base = 196608u + (size_t)L * 262144u + (size_t)(k >> 5) * 32768u;
    }
    const size_t dst = base + (size_t)(k & 31) * 512
                     + (size_t)((((n >> 3) ^ (k & 7))) << 4) + (n & 7) * 2;
    __nv_bfloat16 hi = __float2bfloat16(w);
    float hf = __bfloat162float(hi);
    __nv_bfloat16 lo = __float2bfloat16(w - hf);
    *(__nv_bfloat16*)(gw + dst) = hi;
    *(__nv_bfloat16*)(gw + dst + 16384) = lo;
}

// ---------------- main fused decoder ----------------------------------------
__global__ void __launch_bounds__(NTH, 1)
decoder(const float* __restrict__ points,
        const float* __restrict__ b_in, const float* __restrict__ b_hid,
        const float* __restrict__ w_rgb, const float* __restrict__ b_rgb,
        const float* __restrict__ w_den, const float* __restrict__ b_den,
        const float* __restrict__ w_emb, const float* __restrict__ b_emb,
        float* __restrict__ out) {
    extern __shared__ char sm[];
    const uint32_t smb = smem_u32(sm);
    const int t = threadIdx.x, lane = t & 31, wid = t >> 5;
    const int wm = wid >> 2, wn = wid & 3;        // warp grid 4(M) x 4(N)
    const int g0 = blockIdx.x * PTS;
    const uint8_t* gw = (const uint8_t*)g_wq;

    // kick off weight chunk 0 load (overlaps sampling)
    {
        const uint32_t dst = smb + SO_WBUF;
#pragma unroll
        for (int i = 0; i < 4; i++) {
            const int off = (t + i * NTH) * 16;
            CP_ASYNC16(dst + off, gw + off);
        }
        CP_COMMIT();
    }

    // stage biases + head weights
    float* sb  = (float*)(sm + SO_SB);
    float* wht = (float*)(sm + SO_WHT);
    float* bhd = (float*)(sm + SO_BHD);
    for (int i = t; i < 2560; i += NTH) sb[i] = (i < 256) ? b_in[i] : b_hid[i - 256];
    for (int i = t; i < 256; i += NTH) {
        wht[i * 8 + 0] = w_rgb[i];        wht[i * 8 + 1] = w_rgb[256 + i];
        wht[i * 8 + 2] = w_rgb[512 + i];  wht[i * 8 + 3] = w_den[i];
        wht[i * 8 + 4] = w_emb[i];        wht[i * 8 + 5] = w_emb[256 + i];
        wht[i * 8 + 6] = w_emb[512 + i];  wht[i * 8 + 7] = 0.0f;
    }
    if (t < 3) bhd[t] = b_rgb[t];
    else if (t == 3) bhd[3] = b_den[0];
    else if (t < 7) bhd[t] = b_emb[t - 4];
    else if (t == 7) bhd[7] = 0.0f;

    // ---- sampling: one warp per (point, plane); write bf16 hi/lo into A -----
    for (int task = wid; task < PTS * 3; task += 16) {
        const int p = task / 3, pl = task - p * 3;
        const int g = g0 + p, b = g / NN;
        const float px = points[(size_t)g * 3 + 0];
        const float py = points[(size_t)g * 3 + 1];
        const float pz = points[(size_t)g * 3 + 2];
        float gx, gy;
        if (pl == 0)      { gx = px; gy = py; }
        else if (pl == 1) { gx = px; gy = pz; }
        else              { gx = py; gy = pz; }
        const float ix = (gx + 1.0f) * 0.5f * (float)(WW - 1);
        const float iy = (gy + 1.0f) * 0.5f * (float)(HH - 1);
        const float x0f = floorf(ix), y0f = floorf(iy);
        const float wx = ix - x0f, wy = iy - y0f;
        const int x0 = min(max((int)x0f, 0), WW - 1);
        const int x1 = min(max((int)x0f + 1, 0), WW - 1);
        const int y0 = min(max((int)y0f, 0), HH - 1);
        const int y1 = min(max((int)y0f + 1, 0), HH - 1);
        const float* base = g_trip + (size_t)(b * 3 + pl) * (HH * WW) * CC;
        const float2* c00 = (const float2*)(base + ((size_t)y0 * WW + x0) * CC);
        const float2* c01 = (const float2*)(base + ((size_t)y0 * WW + x1) * CC);
        const float2* c10 = (const float2*)(base + ((size_t)y1 * WW + x0) * CC);
        const float2* c11 = (const float2*)(base + ((size_t)y1 * WW + x1) * CC);
        const float w00 = (1.0f - wx) * (1.0f - wy), w01 = wx * (1.0f - wy);
        const float w10 = (1.0f - wx) * wy,          w11 = wx * wy;
        const float2 v00 = c00[lane], v01 = c01[lane];
        const float2 v10 = c10[lane], v11 = c11[lane];
        float rx = v00.x * w00 + v01.x * w01 + v10.x * w10 + v11.x * w11;
        float ry = v00.y * w00 + v01.y * w01 + v10.y * w10 + v11.y * w11;
        uint32_t hw; PACKBF(hw, rx, ry);
        float h0 = __uint_as_float(hw << 16);
        float h1 = __uint_as_float(hw & 0xFFFF0000u);
        uint32_t lw; PACKBF(lw, rx - h0, ry - h1);
        // word index wc = pl*32 + lane  (k = 2*wc), row p, swizzled
        const int wc = pl * 32 + lane;
        const uint32_t ao = p * 512 + ((((wc >> 2) ^ (p & 7))) << 4) + (wc & 3) * 4;
        *(uint32_t*)(sm + ao) = hw;                 // A hi
        *(uint32_t*)(sm + ao + 65536) = lw;         // A lo
    }
    __syncthreads();

    // ---- 10 layers ----------------------------------------------------------
    int gc = 0;
    const int rowA = wm * 32 + (lane & 15);       // + mi*16
    const uint32_t swA = (uint32_t)(lane & 7);

    for (int L = 0; L < 10; L++) {
        const int nch = (L == 0) ? 6 : 8;
        float acc[2][8][4];
        // bias init (bias of this layer baked into accumulators)
#pragma unroll
        for (int ni = 0; ni < 8; ni++) {
            const int col0 = wn * 64 + ni * 8 + 2 * (lane & 3);
            const float bv0 = sb[L * 256 + col0];
            const float bv1 = sb[L * 256 + col0 + 1];
#pragma unroll
            for (int mi = 0; mi < 2; mi++) {
                acc[mi][ni][0] = bv0; acc[mi][ni][1] = bv1;
                acc[mi][ni][2] = bv0; acc[mi][ni][3] = bv1;
            }
        }

        for (int c = 0; c < nch; c++) {
            CP_WAIT0();
            __syncthreads();
            if (gc + 1 < NCHUNK_TOT) {           // prefetch next chunk
                const uint32_t dst = smb + SO_WBUF + ((gc + 1) & 1) * 32768;
                const uint8_t* src = gw + (size_t)(gc + 1) * 32768;
#pragma unroll
                for (int i = 0; i < 4; i++) {
                    const int off = (t + i * NTH) * 16;
                    CP_ASYNC16(dst + off, src + off);
                }
                CP_COMMIT();
            }
            const uint32_t wb = smb + SO_WBUF + (gc & 1) * 32768;
#pragma unroll
            for (int s = 0; s < 2; s++) {
                const int ku = c * 4 + s * 2;     // A 16B-unit base for this k16
                uint32_t ah[2][4], al[2][4];
#pragma unroll
                for (int mi = 0; mi < 2; mi++) {
                    const uint32_t aA = smb + (rowA + mi * 16) * 512
                                      + ((((uint32_t)(ku + (lane >> 4))) ^ swA) << 4);
                    ldsm4(ah[mi], aA);
                    ldsm4(al[mi], aA + 65536);
                }
                const int rowB = s * 16 + (lane & 15);
#pragma unroll
                for (int nt = 0; nt < 4; nt++) {
                    uint32_t bh[4], bl[4];
                    const uint32_t ub = (uint32_t)(wn * 8 + nt * 2 + (lane >> 4));
                    const uint32_t aB = wb + rowB * 512 + ((ub ^ swA) << 4);
                    ldsm4t(bh, aB);
                    ldsm4t(bl, aB + 16384);
#pragma unroll
                    for (int mi = 0; mi < 2; mi++) {
                        mma16816(acc[mi][2 * nt],     ah[mi], bh);
                        mma16816(acc[mi][2 * nt + 1], ah[mi], bh + 2);
                        mma16816(acc[mi][2 * nt],     al[mi], bh);
                        mma16816(acc[mi][2 * nt + 1], al[mi], bh + 2);
                        mma16816(acc[mi][2 * nt],     ah[mi], bl);
                        mma16816(acc[mi][2 * nt + 1], ah[mi], bl + 2);
                    }
                }
            }
            gc++;
        }
        __syncthreads();   // all warps done reading A for this layer

        if (L < 9) {
            // epilogue: relu + bf16 hi/lo re-split -> A planes (swizzled)
#pragma unroll
            for (int mi = 0; mi < 2; mi++) {
#pragma unroll
                for (int ni = 0; ni < 8; ni++) {
                    float v0 = fmaxf(acc[mi][ni][0], 0.0f);
                    float v1 = fmaxf(acc[mi][ni][1], 0.0f);
                    float v2 = fmaxf(acc[mi][ni][2], 0.0f);
                    float v3 = fmaxf(acc[mi][ni][3], 0.0f);
                    const int r1 = wm * 32 + mi * 16 + (lane >> 2);
                    const uint32_t u = (uint32_t)((wn * 8 + ni) ^ ((lane >> 2) & 7));
                    const uint32_t a1 = r1 * 512 + (u << 4) + (lane & 3) * 4;
                    uint32_t hw, lw;
                    PACKBF(hw, v0, v1);
                    {
                        float h0 = __uint_as_float(hw << 16);
                        float h1 = __uint_as_float(hw & 0xFFFF0000u);
                        PACKBF(lw, v0 - h0, v1 - h1);
                    }
                    *(uint32_t*)(sm + a1) = hw;
                    *(uint32_t*)(sm + a1 + 65536) = lw;
                    PACKBF(hw, v2, v3);
                    {
                        float h0 = __uint_as_float(hw << 16);
                        float h1 = __uint_as_float(hw & 0xFFFF0000u);
                        PACKBF(lw, v2 - h0, v3 - h1);
                    }
                    *(uint32_t*)(sm + a1 + 4096) = hw;            // row +8
                    *(uint32_t*)(sm + a1 + 4096 + 65536) = lw;
                }
            }
        } else {
            // final layer: store fp32 h into A region (plain layout [p][256])
#pragma unroll
            for (int mi = 0; mi < 2; mi++) {
#pragma unroll
                for (int ni = 0; ni < 8; ni++) {
                    const int r1 = wm * 32 + mi * 16 + (lane >> 2);
                    const int col0 = wn * 64 + ni * 8 + 2 * (lane & 3);
                    float* d1 = (float*)(sm + r1 * 1024 + col0 * 4);
                    float* d2 = (float*)(sm + (r1 + 8) * 1024 + col0 * 4);
                    d1[0] = fmaxf(acc[mi][ni][0], 0.0f);
                    d1[1] = fmaxf(acc[mi][ni][1], 0.0f);
                    d2[0] = fmaxf(acc[mi][ni][2], 0.0f);
                    d2[1] = fmaxf(acc[mi][ni][3], 0.0f);
                }
            }
        }
        __syncthreads();
    }

    // ---- heads: rgb(3, sigmoid), density(1), embedding(3) -------------------
    const float* hf = (const float*)sm;           // [128][256] f32
    for (int task = wid; task < PTS * 7; task += 16) {
        const int p = task & 127;
        const int j = task >> 7;                  // 0..6
        const float4* hp = (const float4*)(hf + p * 256);
        float s = 0.0f;
#pragma unroll
        for (int ii = 0; ii < 2; ii++) {
            const float4 hv = hp[lane + ii * 32];
            const int c0 = (lane + ii * 32) * 4;
            s += hv.x * wht[(c0 + 0) * 8 + j] + hv.y * wht[(c0 + 1) * 8 + j]
               + hv.z * wht[(c0 + 2) * 8 + j] + hv.w * wht[(c0 + 3) * 8 + j];
        }
#pragma unroll
        for (int off = 16; off; off >>= 1) s += __shfl_xor_sync(0xFFFFFFFFu, s, off);
        if (lane == 0) {
            s += bhd[j];
            const int g = g0 + p;
            if (j < 3)
                out[(size_t)g * 3 + j] = 1.0f / (1.0f + expf(-s));
            else if (j == 3)
                out[(size_t)BB * NN * 3 + g] = s;
            else
                out[(size_t)BB * NN * 4 + (size_t)g * 3 + (j - 4)] = s;
        }
    }
}

// ---------------------------------------------------------------------------
extern "C" void kernel_launch(void* const* d_in, const int* in_sizes, int n_in,
                              void* d_out, int out_size) {
    const float* triplane = (const float*)d_in[0];
    const float* points   = (const float*)d_in[1];
    const float* w_in     = (const float*)d_in[2];
    const float* b_in     = (const float*)d_in[3];
    const float* w_hid    = (const float*)d_in[4];
    const float* b_hid    = (const float*)d_in[5];
    const float* w_rgb    = (const float*)d_in[6];
    const float* b_rgb    = (const float*)d_in[7];
    const float* w_den    = (const float*)d_in[8];
    const float* b_den    = (const float*)d_in[9];
    const float* w_emb    = (const float*)d_in[10];
    const float* b_emb    = (const float*)d_in[11];
    float* out = (float*)d_out;

    transpose_trip<<<dim3((HH * WW) / 32, BB * 3), 256>>>(triplane);
    prep_weights<<<(49152 + 9 * 65536 + 255) / 256, 256>>>(w_in, w_hid);

    cudaFuncSetAttribute(decoder, cudaFuncAttributeMaxDynamicSharedMemorySize, SMEM_TOT);
    decoder<<<(BB * NN) / PTS, NTH, SMEM_TOT>>>(
        points, b_in, b_hid, w_rgb, b_rgb, w_den, b_den, w_emb, b_emb, out);
}

// round 7
// speedup vs baseline: 1.9426x; 1.0004x over previous
#include <cuda_runtime.h>
#include <math.h>
#include <stdint.h>

// ---------------------------------------------------------------------------
// TriplaneDecoder via int8 double-digit mma.sync (m16n8k32.s8) — compute_100.
// x = s*(d1*128 + d0). D = sa*sb*(16384*S11 + 128*(S1m)) with
// S11 = d1a.d1b, S1m = d1a.d0b + d0a.d1b  (d0a.d0b dropped, ~5e-5/layer).
// CTA = 64 points, 8 warps 2(M)x4(N), warp tile 32x64, K chunked by 32.
// A digits in smem (XOR-swizzled); weights pre-quantized + tile-blocked in
// gmem by prolog -> linear cp.async; per-row A scales recomputed each layer.
// ---------------------------------------------------------------------------

#define BB 4
#define NN 100000
#define CC 64
#define HH 256
#define WW 256
#define PTS 64
#define NTH 256
#define NCHUNK_TOT 78     // L0: 6 chunks (K=192), L1..9: 8 chunks

// smem byte offsets
#define SO_A1    0        // A d1 plane: 64 x 256 s8 (16KB)
#define SO_A0    16384    // A d0 plane (16KB)
#define SO_WBUF  32768    // 2 x 16KB weight chunk buffers (d1 8KB | d0 8KB)
#define SO_ACT   0        // overlay (final f32 acts 64x256 = 64KB)
#define SO_SBIAS 65536    // biases 10*256 f32
#define SO_SB    75776    // weight col scales 10*256 f32
#define SO_WHT   86016    // head weights [256][8] f32
#define SO_RMAX  94208    // rowmax partials [64][4] f32
#define SO_SA    95232    // A row scales, ping-pong [2][64] f32
#define SO_INV   95744    // inv scale [64] f32
#define SO_FAMAX 96000    // feat |max| bits [64] u32
#define SO_BHD   96256    // head biases [8]
#define SMEM_TOT 96288

__device__ float g_trip[(size_t)BB * 3 * HH * WW * CC];
__device__ uint4 g_wq[2555904 / 16];       // quantized blocked weight chunks
__device__ float g_sb[10 * 256];           // per-output weight scales

// ---- PTX helpers -----------------------------------------------------------
__device__ __forceinline__ uint32_t smem_u32(const void* p) {
    uint32_t a;
    asm("{ .reg .u64 t; cvta.to.shared.u64 t, %1; cvt.u32.u64 %0, t; }" : "=r"(a) : "l"(p));
    return a;
}
__device__ __forceinline__ void ldsm4(uint32_t* r, uint32_t a) {
    asm volatile("ldmatrix.sync.aligned.m8n8.x4.shared.b16 {%0,%1,%2,%3}, [%4];"
                 : "=r"(r[0]), "=r"(r[1]), "=r"(r[2]), "=r"(r[3]) : "r"(a));
}
__device__ __forceinline__ void mma_s8(int* c, const uint32_t* a, uint32_t b0, uint32_t b1) {
    asm volatile("mma.sync.aligned.m16n8k32.row.col.s32.s8.s8.s32 "
                 "{%0,%1,%2,%3}, {%4,%5,%6,%7}, {%8,%9}, {%0,%1,%2,%3};"
                 : "+r"(c[0]), "+r"(c[1]), "+r"(c[2]), "+r"(c[3])
                 : "r"(a[0]), "r"(a[1]), "r"(a[2]), "r"(a[3]), "r"(b0), "r"(b1));
}
#define CP_ASYNC16(dst, src) \
    asm volatile("cp.async.cg.shared.global [%0], [%1], 16;" :: "r"(dst), "l"(src))
#define CP_COMMIT() asm volatile("cp.async.commit_group;")
#define CP_WAIT0()  asm volatile("cp.async.wait_group 0;")

// ---------------- prolog 1: triplane [pl][C][HW] -> [pl][HW][C] -------------
__global__ void transpose_trip(const float* __restrict__ in) {
    __shared__ float s[64][33];
    const int plane = blockIdx.y;
    const int hw0 = blockIdx.x * 32;
    const float* ip = in + (size_t)plane * CC * HH * WW;
    float* op = g_trip + (size_t)plane * HH * WW * CC;
    const int t = threadIdx.x, l32 = t & 31, grp = t >> 5;
#pragma unroll
    for (int i = 0; i < 8; i++) {
        int c = grp + i * 8;
        s[c][l32] = ip[(size_t)c * (HH * WW) + hw0 + l32];
    }
    __syncthreads();
    const int c2 = t & 63, r0 = t >> 6;
#pragma unroll
    for (int j = 0; j < 8; j++) {
        int r = r0 + j * 4;
        op[(size_t)(hw0 + r) * CC + c2] = s[c2][r];
    }
}

// ---------------- prolog 2: weight quantization -----------------------------
// one warp per (L, n). chunk layout (16KB = d1 8KB | d0 8KB):
//   plane offset = ((n>>3)*2 + ((k>>4)&1))*128 + (n&7)*16 + (k&15)
__global__ void prep_weights(const float* __restrict__ w_in,
                             const float* __restrict__ w_hid) {
    const int lane = threadIdx.x & 31;
    const int id = blockIdx.x * 8 + (threadIdx.x >> 5);
    if (id >= 2560) return;
    const int L = id >> 8, n = id & 255;
    const int K = (L == 0) ? 192 : 256;
    const size_t lbase = (L == 0) ? 0u : (98304u + (size_t)(L - 1) * 131072u);
    float vals[8];
    float m = 0.0f;
#pragma unroll
    for (int j = 0; j < 8; j++) {
        const int k = lane + j * 32;
        float v = 0.0f;
        if (k < K)
            v = (L == 0) ? w_in[n * 192 + k] : w_hid[(size_t)(L - 1) * 65536 + n * 256 + k];
        vals[j] = v;
        m = fmaxf(m, fabsf(v));
    }
#pragma unroll
    for (int off = 16; off; off >>= 1) m = fmaxf(m, __shfl_xor_sync(0xFFFFFFFFu, m, off));
    const float inv = 16256.0f / fmaxf(m, 1e-30f);
    int8_t* gw = (int8_t*)g_wq;
#pragma unroll
    for (int j = 0; j < 8; j++) {
        const int k = lane + j * 32;
        if (k >= K) break;
        const float q = vals[j] * inv;
        const float d1f = rintf(q * 0.0078125f);
        const int d0 = __float2int_rn(q - 128.0f * d1f);
        const int d1 = (int)d1f;
        const size_t a = lbase + (size_t)(k >> 5) * 16384
                       + (size_t)(((n >> 3) * 2 + ((k >> 4) & 1)) * 128 + (n & 7) * 16 + (k & 15));
        gw[a] = (int8_t)d1;
        gw[a + 8192] = (int8_t)d0;
    }
    if (lane == 0) g_sb[id] = m * (1.0f / 16256.0f);
}

// ---------------- main fused decoder ----------------------------------------
__global__ void __launch_bounds__(NTH, 1)
decoder(const float* __restrict__ points,
        const float* __restrict__ b_in, const float* __restrict__ b_hid,
        const float* __restrict__ w_rgb, const float* __restrict__ b_rgb,
        const float* __restrict__ w_den, const float* __restrict__ b_den,
        const float* __restrict__ w_emb, const float* __restrict__ b_emb,
        float* __restrict__ out) {
    extern __shared__ char sm[];
    const uint32_t smb = smem_u32(sm);
    const int t = threadIdx.x, lane = t & 31, wid = t >> 5;
    const int wm = wid >> 2, wn = wid & 3;     // 2(M) x 4(N)
    const int g0 = blockIdx.x * PTS;
    const uint8_t* gw = (const uint8_t*)g_wq;

    // kick off weight chunk 0 (16KB)
    {
        const uint32_t dst = smb + SO_WBUF;
#pragma unroll
        for (int i = 0; i < 4; i++) {
            const int off = (t + i * NTH) * 16;
            CP_ASYNC16(dst + off, gw + off);
        }
        CP_COMMIT();
    }

    float* sbias = (float*)(sm + SO_SBIAS);
    float* sbs   = (float*)(sm + SO_SB);
    float* wht   = (float*)(sm + SO_WHT);
    float* rmax  = (float*)(sm + SO_RMAX);
    float* saA   = (float*)(sm + SO_SA);       // [2][64]
    float* invs  = (float*)(sm + SO_INV);
    int*   famax = (int*)(sm + SO_FAMAX);
    float* bhd   = (float*)(sm + SO_BHD);

    for (int i = t; i < 2560; i += NTH) {
        sbias[i] = (i < 256) ? b_in[i] : b_hid[i - 256];
        sbs[i] = g_sb[i];
    }
    for (int i = t; i < 256; i += NTH) {
        wht[i * 8 + 0] = w_rgb[i];        wht[i * 8 + 1] = w_rgb[256 + i];
        wht[i * 8 + 2] = w_rgb[512 + i];  wht[i * 8 + 3] = w_den[i];
        wht[i * 8 + 4] = w_emb[i];        wht[i * 8 + 5] = w_emb[256 + i];
        wht[i * 8 + 6] = w_emb[512 + i];  wht[i * 8 + 7] = 0.0f;
    }
    if (t < 64) famax[t] = 0;
    if (t < 3) bhd[t] = b_rgb[t];
    else if (t == 3) bhd[3] = b_den[0];
    else if (t < 7) bhd[t] = b_emb[t - 4];
    else if (t == 7) bhd[7] = 0.0f;
    __syncthreads();

    // ---- sampling phase A: compute feats (kept in regs), per-point |max| ----
    float frx[24], fry[24];
#pragma unroll
    for (int i = 0; i < 24; i++) {
        const int task = wid + i * 8;
        const int p = task / 3, pl = task - p * 3;
        const int g = g0 + p, b = g / NN;
        const float px = points[(size_t)g * 3 + 0];
        const float py = points[(size_t)g * 3 + 1];
        const float pz = points[(size_t)g * 3 + 2];
        float gx, gy;
        if (pl == 0)      { gx = px; gy = py; }
        else if (pl == 1) { gx = px; gy = pz; }
        else              { gx = py; gy = pz; }
        const float ix = (gx + 1.0f) * 0.5f * (float)(WW - 1);
        const float iy = (gy + 1.0f) * 0.5f * (float)(HH - 1);
        const float x0f = floorf(ix), y0f = floorf(iy);
        const float wx = ix - x0f, wy = iy - y0f;
        const int x0 = min(max((int)x0f, 0), WW - 1);
        const int x1 = min(max((int)x0f + 1, 0), WW - 1);
        const int y0 = min(max((int)y0f, 0), HH - 1);
        const int y1 = min(max((int)y0f + 1, 0), HH - 1);
        const float* base = g_trip + (size_t)(b * 3 + pl) * (HH * WW) * CC;
        const float2* c00 = (const float2*)(base + ((size_t)y0 * WW + x0) * CC);
        const float2* c01 = (const float2*)(base + ((size_t)y0 * WW + x1) * CC);
        const float2* c10 = (const float2*)(base + ((size_t)y1 * WW + x0) * CC);
        const float2* c11 = (const float2*)(base + ((size_t)y1 * WW + x1) * CC);
        const float w00 = (1.0f - wx) * (1.0f - wy), w01 = wx * (1.0f - wy);
        const float w10 = (1.0f - wx) * wy,          w11 = wx * wy;
        const float2 v00 = c00[lane], v01 = c01[lane];
        const float2 v10 = c10[lane], v11 = c11[lane];
        const float rx = v00.x * w00 + v01.x * w01 + v10.x * w10 + v11.x * w11;
        const float ry = v00.y * w00 + v01.y * w01 + v10.y * w10 + v11.y * w11;
        frx[i] = rx; fry[i] = ry;
        float am = fmaxf(fabsf(rx), fabsf(ry));
#pragma unroll
        for (int off = 16; off; off >>= 1) am = fmaxf(am, __shfl_xor_sync(0xFFFFFFFFu, am, off));
        if (lane == 0) atomicMax(&famax[p], __float_as_int(am));
    }
    __syncthreads();
    if (t < 64) {
        const float m = __int_as_float(famax[t]);
        saA[t] = m * (1.0f / 16256.0f);                 // sa[0][t]
        invs[t] = 16256.0f / fmaxf(m, 1e-20f);
    }
    __syncthreads();

    // ---- sampling phase B: digitize feats into A planes ---------------------
#pragma unroll
    for (int i = 0; i < 24; i++) {
        const int task = wid + i * 8;
        const int p = task / 3, pl = task - p * 3;
        const float inv = invs[p];
        const float qx = frx[i] * inv, qy = fry[i] * inv;
        const float d1xf = rintf(qx * 0.0078125f), d1yf = rintf(qy * 0.0078125f);
        const int d0x = __float2int_rn(qx - 128.0f * d1xf);
        const int d0y = __float2int_rn(qy - 128.0f * d1yf);
        const int d1x = (int)d1xf, d1y = (int)d1yf;
        const int col0 = pl * 64 + 2 * lane;
        const uint32_t u = (uint32_t)(col0 >> 4);
        const uint32_t base = (uint32_t)p * 256 + ((u ^ (p & 7)) << 4) + (col0 & 15);
        *(uint16_t*)(sm + SO_A1 + base) = (uint16_t)(((d1y & 0xFF) << 8) | (d1x & 0xFF));
        *(uint16_t*)(sm + SO_A0 + base) = (uint16_t)(((d0y & 0xFF) << 8) | (d0x & 0xFF));
    }
    __syncthreads();

    // ---- 10 layers ----------------------------------------------------------
    int gc = 0;
    for (int L = 0; L < 10; L++) {
        const int nch = (L == 0) ? 6 : 8;
        int acc1[2][8][4], accm[2][8][4];
#pragma unroll
        for (int mi = 0; mi < 2; mi++)
#pragma unroll
            for (int ni = 0; ni < 8; ni++)
#pragma unroll
                for (int j = 0; j < 4; j++) { acc1[mi][ni][j] = 0; accm[mi][ni][j] = 0; }

        for (int c = 0; c < nch; c++) {
            CP_WAIT0();
            __syncthreads();
            if (gc + 1 < NCHUNK_TOT) {
                const uint32_t dst = smb + SO_WBUF + ((gc + 1) & 1) * 16384;
                const uint8_t* src = gw + (size_t)(gc + 1) * 16384;
#pragma unroll
                for (int i = 0; i < 4; i++) {
                    const int off = (t + i * NTH) * 16;
                    CP_ASYNC16(dst + off, src + off);
                }
                CP_COMMIT();
            }
            const uint32_t wb = smb + SO_WBUF + (gc & 1) * 16384;

            // A fragments (d1, d0) for this k32
            uint32_t a1[2][4], a0[2][4];
#pragma unroll
            for (int mi = 0; mi < 2; mi++) {
                const uint32_t rA = (uint32_t)(wm * 32 + mi * 16 + (lane & 15));
                const uint32_t aoff = rA * 256
                    + ((((uint32_t)(c * 2 + (lane >> 4)) ^ (rA & 7))) << 4);
                ldsm4(a1[mi], smb + SO_A1 + aoff);
                ldsm4(a0[mi], smb + SO_A0 + aoff);
            }
            // B fragments + MMAs: 4 ldsm.x4 per digit cover 8 n-tiles
            const uint32_t tB = (uint32_t)(lane >> 3);
            const uint32_t rowB = (uint32_t)(lane & 7);
#pragma unroll
            for (int nt2 = 0; nt2 < 4; nt2++) {
                const uint32_t blk = (uint32_t)((wn * 8 + nt2 * 2 + (tB >> 1)) * 2 + (tB & 1));
                const uint32_t boff = blk * 128 + rowB * 16;
                uint32_t bh[4], bl[4];
                ldsm4(bh, wb + boff);
                ldsm4(bl, wb + 8192 + boff);
#pragma unroll
                for (int mi = 0; mi < 2; mi++) {
                    mma_s8(acc1[mi][nt2 * 2],     a1[mi], bh[0], bh[1]);
                    mma_s8(acc1[mi][nt2 * 2 + 1], a1[mi], bh[2], bh[3]);
                    mma_s8(accm[mi][nt2 * 2],     a1[mi], bl[0], bl[1]);
                    mma_s8(accm[mi][nt2 * 2 + 1], a1[mi], bl[2], bl[3]);
                    mma_s8(accm[mi][nt2 * 2],     a0[mi], bh[0], bh[1]);
                    mma_s8(accm[mi][nt2 * 2 + 1], a0[mi], bh[2], bh[3]);
                }
            }
            gc++;
        }
        __syncthreads();   // all warps done reading A planes

        const float* sbl = sbs + L * 256;
        const float* bl_ = sbias + L * 256;
        const float* sap = saA + (L & 1) * 64;

        if (L < 9) {
            // pass 1: row maxima
            float rmx[2][2] = {{0.0f, 0.0f}, {0.0f, 0.0f}};
#pragma unroll
            for (int mi = 0; mi < 2; mi++) {
                const int r1 = wm * 32 + mi * 16 + (lane >> 2);
                const float s0 = sap[r1], s1 = sap[r1 + 8];
#pragma unroll
                for (int ni = 0; ni < 8; ni++) {
                    const int c0 = wn * 64 + ni * 8 + 2 * (lane & 3);
                    const float f0 = sbl[c0], f1 = sbl[c0 + 1];
                    const float b0 = bl_[c0], b1 = bl_[c0 + 1];
                    float v0 = fmaxf(s0 * f0 * (16384.0f * (float)acc1[mi][ni][0] + 128.0f * (float)accm[mi][ni][0]) + b0, 0.0f);
                    float v1 = fmaxf(s0 * f1 * (16384.0f * (float)acc1[mi][ni][1] + 128.0f * (float)accm[mi][ni][1]) + b1, 0.0f);
                    float v2 = fmaxf(s1 * f0 * (16384.0f * (float)acc1[mi][ni][2] + 128.0f * (float)accm[mi][ni][2]) + b0, 0.0f);
                    float v3 = fmaxf(s1 * f1 * (16384.0f * (float)acc1[mi][ni][3] + 128.0f * (float)accm[mi][ni][3]) + b1, 0.0f);
                    rmx[mi][0] = fmaxf(rmx[mi][0], fmaxf(v0, v1));
                    rmx[mi][1] = fmaxf(rmx[mi][1], fmaxf(v2, v3));
                }
            }
#pragma unroll
            for (int d = 1; d <= 2; d <<= 1) {
#pragma unroll
                for (int mi = 0; mi < 2; mi++) {
                    rmx[mi][0] = fmaxf(rmx[mi][0], __shfl_xor_sync(0xFFFFFFFFu, rmx[mi][0], d));
                    rmx[mi][1] = fmaxf(rmx[mi][1], __shfl_xor_sync(0xFFFFFFFFu, rmx[mi][1], d));
                }
            }
            if ((lane & 3) == 0) {
#pragma unroll
                for (int mi = 0; mi < 2; mi++) {
                    rmax[(wm * 32 + mi * 16 + (lane >> 2)) * 4 + wn] = rmx[mi][0];
                    rmax[(wm * 32 + mi * 16 + 8 + (lane >> 2)) * 4 + wn] = rmx[mi][1];
                }
            }
            __syncthreads();
            if (t < 64) {
                const float m = fmaxf(fmaxf(rmax[t * 4], rmax[t * 4 + 1]),
                                      fmaxf(rmax[t * 4 + 2], rmax[t * 4 + 3]));
                saA[((L + 1) & 1) * 64 + t] = m * (1.0f / 16256.0f);
                invs[t] = 16256.0f / fmaxf(m, 1e-20f);
            }
            __syncthreads();
            // pass 2: digitize + store A planes
#pragma unroll
            for (int mi = 0; mi < 2; mi++) {
                const int r1 = wm * 32 + mi * 16 + (lane >> 2);
                const float s0 = sap[r1], s1 = sap[r1 + 8];
                const float i0 = invs[r1], i1 = invs[r1 + 8];
#pragma unroll
                for (int ni = 0; ni < 8; ni++) {
                    const int c0 = wn * 64 + ni * 8 + 2 * (lane & 3);
                    const float f0 = sbl[c0], f1 = sbl[c0 + 1];
                    const float b0 = bl_[c0], b1 = bl_[c0 + 1];
                    float v0 = fmaxf(s0 * f0 * (16384.0f * (float)acc1[mi][ni][0] + 128.0f * (float)accm[mi][ni][0]) + b0, 0.0f);
                    float v1 = fmaxf(s0 * f1 * (16384.0f * (float)acc1[mi][ni][1] + 128.0f * (float)accm[mi][ni][1]) + b1, 0.0f);
                    float v2 = fmaxf(s1 * f0 * (16384.0f * (float)acc1[mi][ni][2] + 128.0f * (float)accm[mi][ni][2]) + b0, 0.0f);
                    float v3 = fmaxf(s1 * f1 * (16384.0f * (float)acc1[mi][ni][3] + 128.0f * (float)accm[mi][ni][3]) + b1, 0.0f);
                    const float q0 = v0 * i0, q1 = v1 * i0, q2 = v2 * i1, q3 = v3 * i1;
                    const float e0 = rintf(q0 * 0.0078125f), e1 = rintf(q1 * 0.0078125f);
                    const float e2 = rintf(q2 * 0.0078125f), e3 = rintf(q3 * 0.0078125f);
                    const int g0i = __float2int_rn(q0 - 128.0f * e0);
                    const int g1i = __float2int_rn(q1 - 128.0f * e1);
                    const int g2i = __float2int_rn(q2 - 128.0f * e2);
                    const int g3i = __float2int_rn(q3 - 128.0f * e3);
                    const uint32_t u = (uint32_t)(c0 >> 4);
                    const uint32_t ba = (uint32_t)r1 * 256 + ((u ^ (r1 & 7)) << 4) + (c0 & 15);
                    *(uint16_t*)(sm + SO_A1 + ba) = (uint16_t)((((int)e1 & 0xFF) << 8) | ((int)e0 & 0xFF));
                    *(uint16_t*)(sm + SO_A0 + ba) = (uint16_t)(((g1i & 0xFF) << 8) | (g0i & 0xFF));
                    *(uint16_t*)(sm + SO_A1 + ba + 2048) = (uint16_t)((((int)e3 & 0xFF) << 8) | ((int)e2 & 0xFF));
                    *(uint16_t*)(sm + SO_A0 + ba + 2048) = (uint16_t)(((g3i & 0xFF) << 8) | (g2i & 0xFF));
                }
            }
        } else {
            // final layer: dequant -> f32 acts at SO_ACT [64][256]
            float* act = (float*)(sm + SO_ACT);
#pragma unroll
            for (int mi = 0; mi < 2; mi++) {
                const int r1 = wm * 32 + mi * 16 + (lane >> 2);
                const float s0 = sap[r1], s1 = sap[r1 + 8];
#pragma unroll
                for (int ni = 0; ni < 8; ni++) {
                    const int c0 = wn * 64 + ni * 8 + 2 * (lane & 3);
                    const float f0 = sbl[c0], f1 = sbl[c0 + 1];
                    const float b0 = bl_[c0], b1 = bl_[c0 + 1];
                    act[r1 * 256 + c0]           = fmaxf(s0 * f0 * (16384.0f * (float)acc1[mi][ni][0] + 128.0f * (float)accm[mi][ni][0]) + b0, 0.0f);
                    act[r1 * 256 + c0 + 1]       = fmaxf(s0 * f1 * (16384.0f * (float)acc1[mi][ni][1] + 128.0f * (float)accm[mi][ni][1]) + b1, 0.0f);
                    act[(r1 + 8) * 256 + c0]     = fmaxf(s1 * f0 * (16384.0f * (float)acc1[mi][ni][2] + 128.0f * (float)accm[mi][ni][2]) + b0, 0.0f);
                    act[(r1 + 8) * 256 + c0 + 1] = fmaxf(s1 * f1 * (16384.0f * (float)acc1[mi][ni][3] + 128.0f * (float)accm[mi][ni][3]) + b1, 0.0f);
                }
            }
        }
        __syncthreads();
    }

    // ---- heads --------------------------------------------------------------
    const float* hf = (const float*)(sm + SO_ACT);
    for (int task = wid; task < PTS * 7; task += 8) {
        const int p = task & 63;
        const int j = task >> 6;
        const float4* hp = (const float4*)(hf + p * 256);
        float s = 0.0f;
#pragma unroll
        for (int ii = 0; ii < 2; ii++) {
            const float4 hv = hp[lane + ii * 32];
            const int c0 = (lane + ii * 32) * 4;
            s += hv.x * wht[(c0 + 0) * 8 + j] + hv.y * wht[(c0 + 1) * 8 + j]
               + hv.z * wht[(c0 + 2) * 8 + j] + hv.w * wht[(c0 + 3) * 8 + j];
        }
#pragma unroll
        for (int off = 16; off; off >>= 1) s += __shfl_xor_sync(0xFFFFFFFFu, s, off);
        if (lane == 0) {
            s += bhd[j];
            const int g = g0 + p;
            if (j < 3)
                out[(size_t)g * 3 + j] = 1.0f / (1.0f + expf(-s));
            else if (j == 3)
                out[(size_t)BB * NN * 3 + g] = s;
            else
                out[(size_t)BB * NN * 4 + (size_t)g * 3 + (j - 4)] = s;
        }
    }
}

// ---------------------------------------------------------------------------
extern "C" void kernel_launch(void* const* d_in, const int* in_sizes, int n_in,
                              void* d_out, int out_size) {
    const float* triplane = (const float*)d_in[0];
    const float* points   = (const float*)d_in[1];
    const float* w_in     = (const float*)d_in[2];
    const float* b_in     = (const float*)d_in[3];
    const float* w_hid    = (const float*)d_in[4];
    const float* b_hid    = (const float*)d_in[5];
    const float* w_rgb    = (const float*)d_in[6];
    const float* b_rgb    = (const float*)d_in[7];
    const float* w_den    = (const float*)d_in[8];
    const float* b_den    = (const float*)d_in[9];
    const float* w_emb    = (const float*)d_in[10];
    const float* b_emb    = (const float*)d_in[11];
    float* out = (float*)d_out;

    transpose_trip<<<dim3((HH * WW) / 32, BB * 3), 256>>>(triplane);
    prep_weights<<<320, 256>>>(w_in, w_hid);

    cudaFuncSetAttribute(decoder, cudaFuncAttributeMaxDynamicSharedMemorySize, SMEM_TOT);
    decoder<<<(BB * NN) / PTS, NTH, SMEM_TOT>>>(
        points, b_in, b_hid, w_rgb, b_rgb, w_den, b_den, w_emb, b_emb, out);
}